// round 15
// baseline (speedup 1.0000x reference)
#include <cuda_runtime.h>
#include <cuda_bf16.h>
#include <cstdint>

#define BATCH 8
#define SQN 512
#define DDIM 32
typedef unsigned short u16;
typedef unsigned int u32;

// scratch (__device__ globals, referenced ONLY inside device code; zero-init)
static __device__ __align__(16) u16 g_F[(size_t)BATCH*SQN*2304];   // q feats [hi|lo]
static __device__ __align__(16) u16 g_G[(size_t)BATCH*SQN*2304];   // k feats [hi|lo]
static __device__ __align__(16) u16 g_S[(size_t)BATCH*SQN*1024];   // score  [hi|lo]
static __device__ __align__(16) u16 g_V[(size_t)BATCH*1152*1024];  // vcov^T + vmean^T [hi|lo]
static __device__ __align__(16) float g_js [(size_t)BATCH*SQN*SQN]; // split-K partial 0
static __device__ __align__(16) float g_js2[(size_t)BATCH*SQN*SQN]; // split-K partial 1

__device__ __forceinline__ u16 f2bf(float x){ __nv_bfloat16 h=__float2bfloat16(x); return *(u16*)&h; }
__device__ __forceinline__ float bf2f(u16 u){ __nv_bfloat16 h=*(__nv_bfloat16*)&u; return __bfloat162float(h); }
__device__ __forceinline__ u32 hilo(float x0,float x1,int lo){
    u16 h0=f2bf(x0), h1=f2bf(x1);
    if(lo){ h0=f2bf(x0-bf2f(h0)); h1=f2bf(x1-bf2f(h1)); }
    return (u32)h0 | ((u32)h1<<16);
}
__device__ __forceinline__ u32 sptr(const void* p){u32 a;asm("{.reg .u64 t;cvta.to.shared.u64 t,%1;cvt.u32.u64 %0,t;}":"=r"(a):"l"(p));return a;}
#define SWZ64(o) ((o)^(((o)>>3)&0x30))

// ---------------------------------------------------------------- featurize
// One warp per matrix (4/block); register-resident Gauss-Jordan; cov staged in smem.
__global__ void __launch_bounds__(128) feat_kernel(
    const float* __restrict__ q_mean,const float* __restrict__ q_cov,
    const float* __restrict__ k_mean,const float* __restrict__ k_cov)
{
    __shared__ float inv_s[4][32*33];
    __shared__ float cov_s[4][32*33];
    __shared__ float mean_sh[4][32];
    __shared__ float u_sh[4][32];
    __shared__ u16 dtab[528];

    const int tid=threadIdx.x, wid=tid>>5, lane=tid&31;
    for(int t=tid;t<528;t+=128){
        int d=0,rem=t,len=32; while(rem>=len){rem-=len;++d;--len;}
        dtab[t]=(u16)((d<<8)|(d+rem));
    }

    const int gidx = blockIdx.x*4 + wid;
    const bool is_k = gidx >= BATCH*SQN;
    const int idx = is_k ? gidx-BATCH*SQN : gidx;
    const float* cov =(is_k?k_cov :q_cov )+(size_t)idx*1024;
    const float* mean=(is_k?k_mean:q_mean)+(size_t)idx*32;

    float m[32];
    #pragma unroll
    for(int i=0;i<8;i++){
        float4 v=*(const float4*)(cov+lane*32+i*4);
        m[i*4]=v.x; m[i*4+1]=v.y; m[i*4+2]=v.z; m[i*4+3]=v.w;
    }
    #pragma unroll
    for(int i=0;i<32;i++) cov_s[wid][lane*33+i]=m[i];
    float mean_v = mean[lane];
    __syncthreads();

    #pragma unroll
    for(int p=0;p<32;p++){
        float colp[32];
        #pragma unroll
        for(int r=0;r<32;r++) colp[r]=__shfl_sync(0xffffffffu,m[r],p);
        float dpi = 1.f/colp[p];
        bool isp = (lane==p);
        float rowp = (isp?1.f:m[p])*dpi;
        m[p]=rowp;
        #pragma unroll
        for(int r=0;r<32;r++){
            if(r==p) continue;
            float base = isp ? 0.f : m[r];
            m[r] = fmaf(-colp[r], rowp, base);
        }
    }

    float u=0.f;
    #pragma unroll
    for(int r=0;r<32;r++) u=fmaf(m[r],__shfl_sync(0xffffffffu,mean_v,r),u);
    float s = u*mean_v;
    #pragma unroll
    for(int o=16;o;o>>=1) s += __shfl_xor_sync(0xffffffffu,s,o);

    #pragma unroll
    for(int r=0;r<32;r++) inv_s[wid][r*33+lane]=m[r];
    mean_sh[wid][lane]=mean_v;
    u_sh[wid][lane]=u;
    __syncwarp();

    const float* iw = inv_s[wid];
    const float* cs = cov_s[wid];
    const float* ms = mean_sh[wid];
    const float* us = u_sh[wid];
    u32* rowp=(u32*)((is_k?g_G:g_F)+(size_t)idx*2304);

    #pragma unroll 1
    for(int i=0;i<18;i++){
        int j=i*32+lane;
        float x0,x1;
        if(j<264){
            #pragma unroll
            for(int h=0;h<2;h++){
                int t=2*j+h;
                u16 de=dtab[t]; int d=de>>8, e=de&255;
                float cv=cs[d*33+e];
                float val=cv+ms[d]*ms[e];
                float iv=iw[d*33+e];
                float dbl=(d==e)?1.f:2.f;
                float x = is_k ? iv : val*dbl;
                if(h) x1=x; else x0=x;
            }
        } else if(j<528){
            #pragma unroll
            for(int h=0;h<2;h++){
                int t=2*j-528+h;
                u16 de=dtab[t]; int d=de>>8, e=de&255;
                float cv=cs[d*33+e];
                float val=cv+ms[d]*ms[e];
                float iv=iw[d*33+e];
                float dbl=(d==e)?1.f:2.f;
                float x = is_k ? val : iv*dbl;
                if(h) x1=x; else x0=x;
            }
        } else if(j<544){
            int r=2*(j-528);
            if(!is_k){ x0=-2.f*ms[r]; x1=-2.f*ms[r+1]; }
            else     { x0=us[r];      x1=us[r+1];      }
        } else if(j<560){
            int r=2*(j-544);
            if(!is_k){ x0=-2.f*us[r]; x1=-2.f*us[r+1]; }
            else     { x0=ms[r];      x1=ms[r+1];      }
        } else if(j==560){
            if(!is_k){ x0=s; x1=1.f; } else { x0=1.f; x1=s; }
        } else { x0=0.f; x1=0.f; }
        rowp[j]    =hilo(x0,x1,0);
        rowp[576+j]=hilo(x0,x1,1);
    }
}

// ---------------------------------------------------------------- vcov transpose+split
__global__ void __launch_bounds__(256) vsplit_kernel(const float* __restrict__ vcov)
{
    __shared__ float ts[64*129];
    const int n0=blockIdx.x*128, k0=blockIdx.y*64, b=blockIdx.z, tid=threadIdx.x;
    const float* src=vcov+((size_t)b*512+k0)*1024+n0;
    for(int i=tid;i<8192;i+=256){ int kk=i>>7,nn=i&127; ts[kk*129+nn]=src[(size_t)kk*1024+nn]; }
    __syncthreads();
    u32* dst=(u32*)g_V;
    for(int i=tid;i<4096;i+=256){
        int nl=i>>5, kp=i&31;
        float x0=ts[(kp*2)*129+nl], x1=ts[(kp*2+1)*129+nl];
        size_t rb=((size_t)b*1152+n0+nl)*512;
        dst[rb+(blockIdx.y*32)+kp]     =hilo(x0,x1,0);
        dst[rb+256+(blockIdx.y*32)+kp] =hilo(x0,x1,1);
    }
}

// ---------------------------------------------------------------- vmean transpose+split
__global__ void __launch_bounds__(256) vmsplit_kernel(const float* __restrict__ vmean)
{
    const int b=blockIdx.x, tid=threadIdx.x;
    for(int i=tid;i<32*512;i+=256){
        int d=i>>9, k=i&511;
        float x=vmean[((size_t)b*512+k)*32+d];
        u16 hi=f2bf(x), lo=f2bf(x-bf2f(hi));
        u16* row=g_V+((size_t)b*1152+1024+d)*1024;
        row[k]=hi; row[512+k]=lo;
    }
}

// ---------------------------------------------------------------- softmax: warp per row; sums split-K partials
__global__ void __launch_bounds__(256) softmax_kernel()
{
    const int tid=threadIdx.x, wid=tid>>5, lane=tid&31;
    const int gid=blockIdx.x*8+wid;
    const float* r1=g_js +(size_t)gid*512;
    const float* r2=g_js2+(size_t)gid*512;
    float4 v[4];
    #pragma unroll
    for(int i=0;i<4;i++){
        float4 a=*(const float4*)(r1+(lane+i*32)*4);
        float4 b=*(const float4*)(r2+(lane+i*32)*4);
        v[i]=make_float4(0.25f*(a.x+b.x),0.25f*(a.y+b.y),0.25f*(a.z+b.z),0.25f*(a.w+b.w));
    }
    float mx=-1e30f;
    #pragma unroll
    for(int i=0;i<4;i++) mx=fmaxf(mx,fmaxf(fmaxf(v[i].x,v[i].y),fmaxf(v[i].z,v[i].w)));
    #pragma unroll
    for(int o=16;o;o>>=1) mx=fmaxf(mx,__shfl_xor_sync(0xffffffffu,mx,o));
    float sum=0.f;
    #pragma unroll
    for(int i=0;i<4;i++){
        v[i].x=__expf(v[i].x-mx); v[i].y=__expf(v[i].y-mx);
        v[i].z=__expf(v[i].z-mx); v[i].w=__expf(v[i].w-mx);
        sum+=v[i].x+v[i].y+v[i].z+v[i].w;
    }
    #pragma unroll
    for(int o=16;o;o>>=1) sum+=__shfl_xor_sync(0xffffffffu,sum,o);
    float inv=1.f/sum;
    u32* srow=(u32*)(g_S+(size_t)gid*1024);
    #pragma unroll
    for(int i=0;i<4;i++){
        float a0=v[i].x*inv, a1=v[i].y*inv, a2=v[i].z*inv, a3=v[i].w*inv;
        uint2 hi=make_uint2(hilo(a0,a1,0),hilo(a2,a3,0));
        uint2 lo=make_uint2(hilo(a0,a1,1),hilo(a2,a3,1));
        *(uint2*)(srow+(lane+i*32)*2)    =hi;
        *(uint2*)(srow+256+(lane+i*32)*2)=lo;
    }
}

// ---------------------------------------------------------------- bf16 mma.sync GEMM v9
// MODE 0: js split-K (A=g_F,B=g_G,C=g_js/g_js2, raw dot products).
// MODE 1: out_cov+out_mean (A=g_S,B=g_V).
// NT, 128x128 CTA tile, 8 warps (32x64 each, unique (wm,wn)), K-chunks of 32.
// 4-stage cp.async pipeline (dynamic smem, 64KB) + fragment double-buffering.
// Reuse: A read 2x, B read 2x per chunk -> smem-BW per FLOP halved vs 128x64.
#define SSTG 16384          // (128+128) rows * 64B
template<int NK,int KCH,int HL,int LDA,int LDB,int NBROWS,int LDC,int MODE,int NBM,int NSPLIT>
__global__ void __launch_bounds__(256,1) gemm_mma(float* __restrict__ Carg,
                                                  float* __restrict__ Cmean)
{
    extern __shared__ __align__(16) u16 smem[];    // 4*SSTG bytes = 65536
    __shared__ int2 offs_s[NK];
    const int tid=threadIdx.x, wid=tid>>5, lane=tid&31;
    const int wm=wid&3, wn=wid>>2;                // warp tile: rows wm*32, cols wn*64
    const int nb=blockIdx.x, mb=blockIdx.y, zz=blockIdx.z;
    const int b   = (NSPLIT==2) ? (zz&(BATCH-1)) : zz;
    const int half= (NSPLIT==2) ? (zz>>3) : 0;
    const u32 sb=sptr(smem);

    const u16* Ag = (MODE==0) ? g_F : g_S;
    const u16* Bg = (MODE==0) ? g_G : g_V;
    float*     Cg = (MODE==0) ? (half ? g_js2 : g_js) : Carg;

    const u16* Ab=Ag+(size_t)(b*512   +mb*128)*LDA;
    const u16* Bb=Bg+(size_t)(b*NBROWS+nb*128)*LDB;

    // K-chunk offset table (global chunk = i + half*NK; kills div/mod in hot loop)
    for(int i=tid;i<NK;i+=256){
        int gt=i+half*NK;
        int blk=gt/KCH, tt=gt-blk*KCH;
        offs_s[i]=make_int2(((blk==2)?HL:0)+tt*32, ((blk==1)?HL:0)+tt*32);
    }

    // per-thread transfer pointers/offsets (A 2 rows + B 2 rows per chunk)
    const int trow=tid>>2, tseg=tid&3;
    const u16* gA0=Ab+(size_t)trow*LDA+tseg*8;
    const u16* gA1=Ab+(size_t)(trow+64)*LDA+tseg*8;
    const u16* gB0=Bb+(size_t)trow*LDB+tseg*8;
    const u16* gB1=Bb+(size_t)(trow+64)*LDB+tseg*8;
    const u32 dA0=SWZ64((u32)(trow*64+tseg*16));
    const u32 dA1=SWZ64((u32)((trow+64)*64+tseg*16));
    const u32 dB0=8192u+dA0;
    const u32 dB1=8192u+dA1;

    auto load=[&](int t,u32 so){
        int2 o=offs_s[t];
        asm volatile("cp.async.cg.shared.global [%0],[%1],16;"::"r"(so+dA0),"l"(gA0+o.x));
        asm volatile("cp.async.cg.shared.global [%0],[%1],16;"::"r"(so+dA1),"l"(gA1+o.x));
        asm volatile("cp.async.cg.shared.global [%0],[%1],16;"::"r"(so+dB0),"l"(gB0+o.y));
        asm volatile("cp.async.cg.shared.global [%0],[%1],16;"::"r"(so+dB1),"l"(gB1+o.y));
        asm volatile("cp.async.commit_group;":::"memory");
    };

    // lane-constant ldmatrix byte offsets within a stage
    const int lr=lane&15, lc=(lane>>4)*8;
    u32 aof[2][2], bof[4][2];
    #pragma unroll
    for(int f=0;f<2;f++)
        #pragma unroll
        for(int ks=0;ks<2;ks++)
            aof[f][ks]=SWZ64((u32)((wm*32+f*16+lr)*64 + (ks*16+lc)*2));
    #pragma unroll
    for(int g2=0;g2<4;g2++)
        #pragma unroll
        for(int ks=0;ks<2;ks++)
            bof[g2][ks]=8192u+SWZ64((u32)((wn*64+g2*16+lr)*64 + (ks*16+lc)*2));

    // fragment double buffers
    u32 fa[2][2][4], fb[2][4][4];
    auto ldfrag=[&](int buf,u32 s0,int ks){
        #pragma unroll
        for(int f=0;f<2;f++)
            asm volatile("ldmatrix.sync.aligned.m8n8.x4.shared.b16 {%0,%1,%2,%3},[%4];"
                :"=r"(fa[buf][f][0]),"=r"(fa[buf][f][1]),"=r"(fa[buf][f][2]),"=r"(fa[buf][f][3])
                :"r"(s0+aof[f][ks]));
        #pragma unroll
        for(int g2=0;g2<4;g2++)
            asm volatile("ldmatrix.sync.aligned.m8n8.x4.shared.b16 {%0,%1,%2,%3},[%4];"
                :"=r"(fb[buf][g2][0]),"=r"(fb[buf][g2][1]),"=r"(fb[buf][g2][2]),"=r"(fb[buf][g2][3])
                :"r"(s0+bof[g2][ks]));
    };

    float acc[2][8][4];
    #pragma unroll
    for(int f=0;f<2;f++)
        #pragma unroll
        for(int n=0;n<8;n++)
            #pragma unroll
            for(int e=0;e<4;e++) acc[f][n][e]=0.f;

    auto mmab=[&](int buf){
        #pragma unroll
        for(int f=0;f<2;f++)
            #pragma unroll
            for(int n=0;n<8;n++)
                asm volatile("mma.sync.aligned.m16n8k16.row.col.f32.bf16.bf16.f32 "
                    "{%0,%1,%2,%3},{%4,%5,%6,%7},{%8,%9},{%0,%1,%2,%3};"
                    :"+f"(acc[f][n][0]),"+f"(acc[f][n][1]),"+f"(acc[f][n][2]),"+f"(acc[f][n][3])
                    :"r"(fa[buf][f][0]),"r"(fa[buf][f][1]),"r"(fa[buf][f][2]),"r"(fa[buf][f][3]),
                     "r"(fb[buf][n>>1][n&1]),"r"(fb[buf][n>>1][(n&1)+2]));
    };

    __syncthreads();   // offs_s ready
    load(0,sb); load(1,sb+SSTG); load(2,sb+2*SSTG);
    asm volatile("cp.async.wait_group 2;":::"memory");
    __syncthreads();                       // stage 0 ready for all warps
    ldfrag(0,sb,0);                        // frags (chunk0, ks0)
    int cur=0, nxt=3;

    #pragma unroll 1
    for(int t=0;t<NK;t++){
        const u32 s0=sb+cur*SSTG;
        ldfrag(1,s0,1);                    // frags (t,ks1) — overlaps mma below
        mmab(0);                           // mma (t,ks0)
        if(t+3<NK){ load(t+3, sb+nxt*SSTG); nxt=(nxt+1)&3; }
        if(t+1<NK){
            if(NK-1-t>=3)      asm volatile("cp.async.wait_group 2;":::"memory");
            else if(NK-1-t==2) asm volatile("cp.async.wait_group 1;":::"memory");
            else               asm volatile("cp.async.wait_group 0;":::"memory");
            __syncthreads();               // stage t+1 visible to all warps
            cur=(cur+1)&3;
            ldfrag(0, sb+cur*SSTG, 0);     // frags (t+1,ks0) — overlaps mma below
        }
        mmab(1);                           // mma (t,ks1)
    }

    const int fr=lane>>2, fc=lane&3;
    if(MODE==1 && nb==NBM){
        // mean tile: B rows 1024..1055 are vmean^T; only cols 0..31 valid
        if(wn!=0) return;
        float* Cb=Cmean+((size_t)(b*512+mb*128+wm*32))*32;
        #pragma unroll
        for(int f=0;f<2;f++)
            #pragma unroll
            for(int n=0;n<4;n++){
                *(float2*)(Cb+(size_t)(f*16+fr  )*32+n*8+fc*2)=make_float2(acc[f][n][0],acc[f][n][1]);
                *(float2*)(Cb+(size_t)(f*16+fr+8)*32+n*8+fc*2)=make_float2(acc[f][n][2],acc[f][n][3]);
            }
        return;
    }

    float* Cb=Cg+((size_t)(b*512+mb*128+wm*32))*LDC + nb*128 + wn*64;
    #pragma unroll
    for(int f=0;f<2;f++)
        #pragma unroll
        for(int n=0;n<8;n++){
            *(float2*)(Cb+(size_t)(f*16+fr  )*LDC+n*8+fc*2)=make_float2(acc[f][n][0],acc[f][n][1]);
            *(float2*)(Cb+(size_t)(f*16+fr+8)*LDC+n*8+fc*2)=make_float2(acc[f][n][2],acc[f][n][3]);
        }
}

// ---------------------------------------------------------------- launch
extern "C" void kernel_launch(void* const* d_in, const int* in_sizes, int n_in,
                              void* d_out, int out_size)
{
    const float* q_mean=(const float*)d_in[0];
    const float* q_cov =(const float*)d_in[1];
    const float* k_mean=(const float*)d_in[2];
    const float* k_cov =(const float*)d_in[3];
    const float* v_mean=(const float*)d_in[4];
    const float* v_cov =(const float*)d_in[5];
    float* out=(float*)d_out;

    auto kjs  = gemm_mma<54,36,1152,2304,2304,512,512,0,-1,2>;
    auto kcov = gemm_mma<48,16,512,1024,1024,1152,1024,1,8,1>;
    cudaFuncSetAttribute(kjs,  cudaFuncAttributeMaxDynamicSharedMemorySize, 4*SSTG);
    cudaFuncSetAttribute(kcov, cudaFuncAttributeMaxDynamicSharedMemorySize, 4*SSTG);

    feat_kernel<<<2*BATCH*SQN/4,128>>>(q_mean,q_cov,k_mean,k_cov);
    vsplit_kernel<<<dim3(8,8,BATCH),256>>>(v_cov);
    vmsplit_kernel<<<BATCH,256>>>(v_mean);
    // js split-K=2: 54 chunks per half; 128x128 tiles -> grid 4x4x16 = 256
    kjs<<<dim3(4,4,BATCH*2),256,4*SSTG>>>(nullptr,nullptr);
    softmax_kernel<<<BATCH*SQN/8,256>>>();
    // out_cov (+fused out_mean as 9th N-tile): 48 chunks; grid 9x4x8 = 288
    kcov<<<dim3(9,4,BATCH),256,4*SSTG>>>(out+(size_t)BATCH*SQN*DDIM, out);
}

// round 16
// speedup vs baseline: 1.2574x; 1.2574x over previous
#include <cuda_runtime.h>
#include <cuda_fp16.h>
#include <cstdint>

#define BATCH 8
#define SQN 512
#define DDIM 32
typedef unsigned short u16;
typedef unsigned int u32;

// scratch (__device__ globals, referenced ONLY inside device code; zero-init)
static __device__ __align__(16) u16 g_F[(size_t)BATCH*SQN*2304];   // q feats [hi|lo] fp16
static __device__ __align__(16) u16 g_G[(size_t)BATCH*SQN*2304];   // k feats [hi|lo] fp16
static __device__ __align__(16) u16 g_S[(size_t)BATCH*SQN*512];    // score hi fp16
static __device__ __align__(16) u16 g_V[(size_t)BATCH*1152*1024];  // vcov^T/vmean^T [hi|lo] fp16
static __device__ __align__(16) float g_js [(size_t)BATCH*SQN*SQN]; // split-K partial 0
static __device__ __align__(16) float g_js2[(size_t)BATCH*SQN*SQN]; // split-K partial 1

__device__ __forceinline__ u16 f2h(float x){ __half h=__float2half(x); return *(u16*)&h; }
__device__ __forceinline__ float h2f(u16 u){ __half h=*(__half*)&u; return __half2float(h); }
__device__ __forceinline__ u32 hilo(float x0,float x1,int lo){
    u16 h0=f2h(x0), h1=f2h(x1);
    if(lo){ h0=f2h(x0-h2f(h0)); h1=f2h(x1-h2f(h1)); }
    return (u32)h0 | ((u32)h1<<16);
}
__device__ __forceinline__ u32 sptr(const void* p){u32 a;asm("{.reg .u64 t;cvta.to.shared.u64 t,%1;cvt.u32.u64 %0,t;}":"=r"(a):"l"(p));return a;}
#define SWZ64(o) ((o)^(((o)>>3)&0x30))

// ---------------------------------------------------------------- featurize
// One warp per matrix (4/block); register-resident Gauss-Jordan; cov staged in smem.
__global__ void __launch_bounds__(128) feat_kernel(
    const float* __restrict__ q_mean,const float* __restrict__ q_cov,
    const float* __restrict__ k_mean,const float* __restrict__ k_cov)
{
    __shared__ float inv_s[4][32*33];
    __shared__ float cov_s[4][32*33];
    __shared__ float mean_sh[4][32];
    __shared__ float u_sh[4][32];
    __shared__ u16 dtab[528];

    const int tid=threadIdx.x, wid=tid>>5, lane=tid&31;
    for(int t=tid;t<528;t+=128){
        int d=0,rem=t,len=32; while(rem>=len){rem-=len;++d;--len;}
        dtab[t]=(u16)((d<<8)|(d+rem));
    }

    const int gidx = blockIdx.x*4 + wid;
    const bool is_k = gidx >= BATCH*SQN;
    const int idx = is_k ? gidx-BATCH*SQN : gidx;
    const float* cov =(is_k?k_cov :q_cov )+(size_t)idx*1024;
    const float* mean=(is_k?k_mean:q_mean)+(size_t)idx*32;

    float m[32];
    #pragma unroll
    for(int i=0;i<8;i++){
        float4 v=*(const float4*)(cov+lane*32+i*4);
        m[i*4]=v.x; m[i*4+1]=v.y; m[i*4+2]=v.z; m[i*4+3]=v.w;
    }
    #pragma unroll
    for(int i=0;i<32;i++) cov_s[wid][lane*33+i]=m[i];
    float mean_v = mean[lane];
    __syncthreads();

    #pragma unroll
    for(int p=0;p<32;p++){
        float colp[32];
        #pragma unroll
        for(int r=0;r<32;r++) colp[r]=__shfl_sync(0xffffffffu,m[r],p);
        float dpi = 1.f/colp[p];
        bool isp = (lane==p);
        float rowp = (isp?1.f:m[p])*dpi;
        m[p]=rowp;
        #pragma unroll
        for(int r=0;r<32;r++){
            if(r==p) continue;
            float base = isp ? 0.f : m[r];
            m[r] = fmaf(-colp[r], rowp, base);
        }
    }

    float u=0.f;
    #pragma unroll
    for(int r=0;r<32;r++) u=fmaf(m[r],__shfl_sync(0xffffffffu,mean_v,r),u);
    float s = u*mean_v;
    #pragma unroll
    for(int o=16;o;o>>=1) s += __shfl_xor_sync(0xffffffffu,s,o);

    #pragma unroll
    for(int r=0;r<32;r++) inv_s[wid][r*33+lane]=m[r];
    mean_sh[wid][lane]=mean_v;
    u_sh[wid][lane]=u;
    __syncwarp();

    const float* iw = inv_s[wid];
    const float* cs = cov_s[wid];
    const float* ms = mean_sh[wid];
    const float* us = u_sh[wid];
    u32* rowp=(u32*)((is_k?g_G:g_F)+(size_t)idx*2304);

    #pragma unroll 1
    for(int i=0;i<18;i++){
        int j=i*32+lane;
        float x0,x1;
        if(j<264){
            #pragma unroll
            for(int h=0;h<2;h++){
                int t=2*j+h;
                u16 de=dtab[t]; int d=de>>8, e=de&255;
                float cv=cs[d*33+e];
                float val=cv+ms[d]*ms[e];
                float iv=iw[d*33+e];
                float dbl=(d==e)?1.f:2.f;
                float x = is_k ? iv : val*dbl;
                if(h) x1=x; else x0=x;
            }
        } else if(j<528){
            #pragma unroll
            for(int h=0;h<2;h++){
                int t=2*j-528+h;
                u16 de=dtab[t]; int d=de>>8, e=de&255;
                float cv=cs[d*33+e];
                float val=cv+ms[d]*ms[e];
                float iv=iw[d*33+e];
                float dbl=(d==e)?1.f:2.f;
                float x = is_k ? val : iv*dbl;
                if(h) x1=x; else x0=x;
            }
        } else if(j<544){
            int r=2*(j-528);
            if(!is_k){ x0=-2.f*ms[r]; x1=-2.f*ms[r+1]; }
            else     { x0=us[r];      x1=us[r+1];      }
        } else if(j<560){
            int r=2*(j-544);
            if(!is_k){ x0=-2.f*us[r]; x1=-2.f*us[r+1]; }
            else     { x0=ms[r];      x1=ms[r+1];      }
        } else if(j==560){
            if(!is_k){ x0=s; x1=1.f; } else { x0=1.f; x1=s; }
        } else { x0=0.f; x1=0.f; }
        rowp[j]    =hilo(x0,x1,0);
        rowp[576+j]=hilo(x0,x1,1);
    }
}

// ---------------------------------------------------------------- vcov transpose+split
__global__ void __launch_bounds__(256) vsplit_kernel(const float* __restrict__ vcov)
{
    __shared__ float ts[64*129];
    const int n0=blockIdx.x*128, k0=blockIdx.y*64, b=blockIdx.z, tid=threadIdx.x;
    const float* src=vcov+((size_t)b*512+k0)*1024+n0;
    for(int i=tid;i<8192;i+=256){ int kk=i>>7,nn=i&127; ts[kk*129+nn]=src[(size_t)kk*1024+nn]; }
    __syncthreads();
    u32* dst=(u32*)g_V;
    for(int i=tid;i<4096;i+=256){
        int nl=i>>5, kp=i&31;
        float x0=ts[(kp*2)*129+nl], x1=ts[(kp*2+1)*129+nl];
        size_t rb=((size_t)b*1152+n0+nl)*512;
        dst[rb+(blockIdx.y*32)+kp]     =hilo(x0,x1,0);
        dst[rb+256+(blockIdx.y*32)+kp] =hilo(x0,x1,1);
    }
}

// ---------------------------------------------------------------- vmean transpose+split
__global__ void __launch_bounds__(256) vmsplit_kernel(const float* __restrict__ vmean)
{
    const int b=blockIdx.x, tid=threadIdx.x;
    for(int i=tid;i<32*512;i+=256){
        int d=i>>9, k=i&511;
        float x=vmean[((size_t)b*512+k)*32+d];
        u16 hi=f2h(x), lo=f2h(x-h2f(hi));
        u16* row=g_V+((size_t)b*1152+1024+d)*1024;
        row[k]=hi; row[512+k]=lo;
    }
}

// ---------------------------------------------------------------- softmax: warp per row; sums split-K partials; emits fp16 hi only
__global__ void __launch_bounds__(256) softmax_kernel()
{
    const int tid=threadIdx.x, wid=tid>>5, lane=tid&31;
    const int gid=blockIdx.x*8+wid;
    const float* r1=g_js +(size_t)gid*512;
    const float* r2=g_js2+(size_t)gid*512;
    float4 v[4];
    #pragma unroll
    for(int i=0;i<4;i++){
        float4 a=*(const float4*)(r1+(lane+i*32)*4);
        float4 b=*(const float4*)(r2+(lane+i*32)*4);
        v[i]=make_float4(0.25f*(a.x+b.x),0.25f*(a.y+b.y),0.25f*(a.z+b.z),0.25f*(a.w+b.w));
    }
    float mx=-1e30f;
    #pragma unroll
    for(int i=0;i<4;i++) mx=fmaxf(mx,fmaxf(fmaxf(v[i].x,v[i].y),fmaxf(v[i].z,v[i].w)));
    #pragma unroll
    for(int o=16;o;o>>=1) mx=fmaxf(mx,__shfl_xor_sync(0xffffffffu,mx,o));
    float sum=0.f;
    #pragma unroll
    for(int i=0;i<4;i++){
        v[i].x=__expf(v[i].x-mx); v[i].y=__expf(v[i].y-mx);
        v[i].z=__expf(v[i].z-mx); v[i].w=__expf(v[i].w-mx);
        sum+=v[i].x+v[i].y+v[i].z+v[i].w;
    }
    #pragma unroll
    for(int o=16;o;o>>=1) sum+=__shfl_xor_sync(0xffffffffu,sum,o);
    float inv=1.f/sum;
    u32* srow=(u32*)(g_S+(size_t)gid*512);
    #pragma unroll
    for(int i=0;i<4;i++){
        float a0=v[i].x*inv, a1=v[i].y*inv, a2=v[i].z*inv, a3=v[i].w*inv;
        uint2 hi=make_uint2(hilo(a0,a1,0),hilo(a2,a3,0));
        *(uint2*)(srow+(lane+i*32)*2)=hi;
    }
}

// ---------------------------------------------------------------- fp16 mma.sync GEMM
// MODE 0: js split-K, 3 K-blocks [FhiGhi|FhiGlo|FloGhi] (A=g_F,B=g_G,C=g_js/g_js2).
// MODE 1: out_cov+out_mean, 2 K-blocks [ShiVhi|ShiVlo] (A=g_S,B=g_V).
// NT, 128x64 CTA tile, 8 warps (32x32), K-chunks of 32.
// 4-stage cp.async pipeline (wait_group 2) + fragment double-buffering.
#define SSTG 12288          // (128+64) rows * 64B
template<int NK,int KCH,int HL,int LDA,int LDB,int NBROWS,int LDC,int MODE,int NBM,int NSPLIT>
__global__ void __launch_bounds__(256,2) gemm_mma(float* __restrict__ Carg,
                                                  float* __restrict__ Cmean)
{
    __shared__ __align__(16) u16 smem[4*SSTG/2];   // 49152 bytes
    __shared__ int2 offs_s[NK];
    const int tid=threadIdx.x, wid=tid>>5, lane=tid&31;
    const int wm=wid&3, wn=wid>>2;                // warp tile: rows wm*32, cols wn*32
    const int nb=blockIdx.x, mb=blockIdx.y, zz=blockIdx.z;
    const int b   = (NSPLIT==2) ? (zz&(BATCH-1)) : zz;
    const int half= (NSPLIT==2) ? (zz>>3) : 0;
    const u32 sb=sptr(smem);

    const u16* Ag = (MODE==0) ? g_F : g_S;
    const u16* Bg = (MODE==0) ? g_G : g_V;
    float*     Cg = (MODE==0) ? (half ? g_js2 : g_js) : Carg;

    const u16* Ab=Ag+(size_t)(b*512   +mb*128)*LDA;
    const u16* Bb=Bg+(size_t)(b*NBROWS+nb*64 )*LDB;

    // K-chunk offset table
    for(int i=tid;i<NK;i+=256){
        int gt=i+half*NK;
        int blk=gt/KCH, tt=gt-blk*KCH;
        if(MODE==0) offs_s[i]=make_int2(((blk==2)?HL:0)+tt*32, ((blk==1)?HL:0)+tt*32);
        else        offs_s[i]=make_int2(tt*32, blk*HL+tt*32);   // A reads Shi both blocks
    }

    // per-thread transfer pointers/offsets
    const int trow=tid>>2, tseg=tid&3;
    const u16* gA0=Ab+(size_t)trow*LDA+tseg*8;
    const u16* gA1=Ab+(size_t)(trow+64)*LDA+tseg*8;
    const u16* gB =Bb+(size_t)trow*LDB+tseg*8;
    const u32 dA0=SWZ64((u32)(trow*64+tseg*16));
    const u32 dA1=SWZ64((u32)((trow+64)*64+tseg*16));
    const u32 dB =8192u+SWZ64((u32)(trow*64+tseg*16));

    auto load=[&](int t,u32 so){
        int2 o=offs_s[t];
        asm volatile("cp.async.cg.shared.global [%0],[%1],16;"::"r"(so+dA0),"l"(gA0+o.x));
        asm volatile("cp.async.cg.shared.global [%0],[%1],16;"::"r"(so+dA1),"l"(gA1+o.x));
        asm volatile("cp.async.cg.shared.global [%0],[%1],16;"::"r"(so+dB ),"l"(gB +o.y));
        asm volatile("cp.async.commit_group;":::"memory");
    };

    // lane-constant ldmatrix byte offsets within a stage
    const int lr=lane&15, lc=(lane>>4)*8;
    u32 aof[2][2], bof[2][2];
    #pragma unroll
    for(int f=0;f<2;f++)
        #pragma unroll
        for(int ks=0;ks<2;ks++)
            aof[f][ks]=SWZ64((u32)((wm*32+f*16+lr)*64 + (ks*16+lc)*2));
    #pragma unroll
    for(int g2=0;g2<2;g2++)
        #pragma unroll
        for(int ks=0;ks<2;ks++)
            bof[g2][ks]=8192u+SWZ64((u32)((wn*32+g2*16+lr)*64 + (ks*16+lc)*2));

    // fragment double buffers
    u32 fa[2][2][4], fb[2][2][4];
    auto ldfrag=[&](int buf,u32 s0,int ks){
        #pragma unroll
        for(int f=0;f<2;f++)
            asm volatile("ldmatrix.sync.aligned.m8n8.x4.shared.b16 {%0,%1,%2,%3},[%4];"
                :"=r"(fa[buf][f][0]),"=r"(fa[buf][f][1]),"=r"(fa[buf][f][2]),"=r"(fa[buf][f][3])
                :"r"(s0+aof[f][ks]));
        #pragma unroll
        for(int g2=0;g2<2;g2++)
            asm volatile("ldmatrix.sync.aligned.m8n8.x4.shared.b16 {%0,%1,%2,%3},[%4];"
                :"=r"(fb[buf][g2][0]),"=r"(fb[buf][g2][1]),"=r"(fb[buf][g2][2]),"=r"(fb[buf][g2][3])
                :"r"(s0+bof[g2][ks]));
    };

    float acc[2][4][4];
    #pragma unroll
    for(int f=0;f<2;f++)
        #pragma unroll
        for(int n=0;n<4;n++)
            #pragma unroll
            for(int e=0;e<4;e++) acc[f][n][e]=0.f;

    auto mmab=[&](int buf){
        #pragma unroll
        for(int f=0;f<2;f++)
            #pragma unroll
            for(int n=0;n<4;n++)
                asm volatile("mma.sync.aligned.m16n8k16.row.col.f32.f16.f16.f32 "
                    "{%0,%1,%2,%3},{%4,%5,%6,%7},{%8,%9},{%0,%1,%2,%3};"
                    :"+f"(acc[f][n][0]),"+f"(acc[f][n][1]),"+f"(acc[f][n][2]),"+f"(acc[f][n][3])
                    :"r"(fa[buf][f][0]),"r"(fa[buf][f][1]),"r"(fa[buf][f][2]),"r"(fa[buf][f][3]),
                     "r"(fb[buf][n>>1][n&1]),"r"(fb[buf][n>>1][(n&1)+2]));
    };

    __syncthreads();   // offs_s ready
    load(0,sb); load(1,sb+SSTG); load(2,sb+2*SSTG);
    asm volatile("cp.async.wait_group 2;":::"memory");
    __syncthreads();                       // stage 0 ready for all warps
    ldfrag(0,sb,0);                        // frags (chunk0, ks0)
    int cur=0, nxt=3;

    #pragma unroll 1
    for(int t=0;t<NK;t++){
        const u32 s0=sb+cur*SSTG;
        ldfrag(1,s0,1);                    // frags (t,ks1) — overlaps mma below
        mmab(0);                           // mma (t,ks0)
        if(t+3<NK){ load(t+3, sb+nxt*SSTG); nxt=(nxt+1)&3; }
        if(t+1<NK){
            if(NK-1-t>=3)      asm volatile("cp.async.wait_group 2;":::"memory");
            else if(NK-1-t==2) asm volatile("cp.async.wait_group 1;":::"memory");
            else               asm volatile("cp.async.wait_group 0;":::"memory");
            __syncthreads();               // stage t+1 visible to all warps
            cur=(cur+1)&3;
            ldfrag(0, sb+cur*SSTG, 0);     // frags (t+1,ks0) — overlaps mma below
        }
        mmab(1);                           // mma (t,ks1)
    }

    const int fr=lane>>2, fc=lane&3;
    if(MODE==1 && nb==NBM){
        if(wn!=0) return;   // only cols 0..31 valid (vmean^T rows 1024..1055)
        float* Cb=Cmean+((size_t)(b*512+mb*128+wm*32))*32;
        #pragma unroll
        for(int f=0;f<2;f++)
            #pragma unroll
            for(int n=0;n<4;n++){
                *(float2*)(Cb+(size_t)(f*16+fr  )*32+n*8+fc*2)=make_float2(acc[f][n][0],acc[f][n][1]);
                *(float2*)(Cb+(size_t)(f*16+fr+8)*32+n*8+fc*2)=make_float2(acc[f][n][2],acc[f][n][3]);
            }
        return;
    }

    float* Cb=Cg+((size_t)(b*512+mb*128+wm*32))*LDC + nb*64 + wn*32;
    #pragma unroll
    for(int f=0;f<2;f++)
        #pragma unroll
        for(int n=0;n<4;n++){
            *(float2*)(Cb+(size_t)(f*16+fr  )*LDC+n*8+fc*2)=make_float2(acc[f][n][0],acc[f][n][1]);
            *(float2*)(Cb+(size_t)(f*16+fr+8)*LDC+n*8+fc*2)=make_float2(acc[f][n][2],acc[f][n][3]);
        }
}

// ---------------------------------------------------------------- launch
extern "C" void kernel_launch(void* const* d_in, const int* in_sizes, int n_in,
                              void* d_out, int out_size)
{
    const float* q_mean=(const float*)d_in[0];
    const float* q_cov =(const float*)d_in[1];
    const float* k_mean=(const float*)d_in[2];
    const float* k_cov =(const float*)d_in[3];
    const float* v_mean=(const float*)d_in[4];
    const float* v_cov =(const float*)d_in[5];
    float* out=(float*)d_out;

    // max shared-memory carveout for GEMM residency
    cudaFuncSetAttribute(gemm_mma<54,36,1152,2304,2304,512,512,0,-1,2>,
                         cudaFuncAttributePreferredSharedMemoryCarveout, 100);
    cudaFuncSetAttribute(gemm_mma<32,16,512,512,1024,1152,1024,1,16,1>,
                         cudaFuncAttributePreferredSharedMemoryCarveout, 100);

    feat_kernel<<<2*BATCH*SQN/4,128>>>(q_mean,q_cov,k_mean,k_cov);
    vsplit_kernel<<<dim3(8,8,BATCH),256>>>(v_cov);
    vmsplit_kernel<<<BATCH,256>>>(v_mean);
    // js split-K=2: 54 chunks per half; grid 8x4x16 = 512 CTAs
    gemm_mma<54,36,1152,2304,2304,512,512,0,-1,2>
        <<<dim3(8,4,BATCH*2),256>>>(nullptr,nullptr);
    softmax_kernel<<<BATCH*SQN/8,256>>>();
    // out_cov (+fused out_mean as 17th N-tile): 2 K-blocks -> 32 chunks; grid 544
    gemm_mma<32,16,512,512,1024,1152,1024,1,16,1>
        <<<dim3(17,4,BATCH),256>>>(out+(size_t)BATCH*SQN*DDIM, out);
}

// round 17
// speedup vs baseline: 1.3195x; 1.0494x over previous
#include <cuda_runtime.h>
#include <cuda_fp16.h>
#include <cstdint>

#define BATCH 8
#define SQN 512
#define DDIM 32
typedef unsigned short u16;
typedef unsigned int u32;

// scratch (__device__ globals, referenced ONLY inside device code; zero-init)
static __device__ __align__(16) u16 g_F[(size_t)BATCH*SQN*2304];   // q feats [hi|lo] fp16
static __device__ __align__(16) u16 g_G[(size_t)BATCH*SQN*2304];   // k feats [hi|lo] fp16
static __device__ __align__(16) u16 g_S[(size_t)BATCH*SQN*512];    // score hi fp16
static __device__ __align__(16) u16 g_V[(size_t)BATCH*1152*1024];  // vcov^T/vmean^T [hi|lo] fp16
static __device__ __align__(16) float g_js [(size_t)BATCH*SQN*SQN]; // split-K partial 0
static __device__ __align__(16) float g_js2[(size_t)BATCH*SQN*SQN]; // split-K partial 1

__device__ __forceinline__ u16 f2h(float x){ __half h=__float2half(x); return *(u16*)&h; }
__device__ __forceinline__ float h2f(u16 u){ __half h=*(__half*)&u; return __half2float(h); }
__device__ __forceinline__ u32 hilo(float x0,float x1,int lo){
    u16 h0=f2h(x0), h1=f2h(x1);
    if(lo){ h0=f2h(x0-h2f(h0)); h1=f2h(x1-h2f(h1)); }
    return (u32)h0 | ((u32)h1<<16);
}
__device__ __forceinline__ u32 sptr(const void* p){u32 a;asm("{.reg .u64 t;cvta.to.shared.u64 t,%1;cvt.u32.u64 %0,t;}":"=r"(a):"l"(p));return a;}
#define SWZ64(o) ((o)^(((o)>>3)&0x30))

// ---------------------------------------------------------------- featurize
// One warp per matrix (4/block); register-resident Gauss-Jordan; cov staged in smem.
__global__ void __launch_bounds__(128) feat_kernel(
    const float* __restrict__ q_mean,const float* __restrict__ q_cov,
    const float* __restrict__ k_mean,const float* __restrict__ k_cov)
{
    __shared__ float inv_s[4][32*33];
    __shared__ float cov_s[4][32*33];
    __shared__ float mean_sh[4][32];
    __shared__ float u_sh[4][32];
    __shared__ u16 dtab[528];

    const int tid=threadIdx.x, wid=tid>>5, lane=tid&31;
    for(int t=tid;t<528;t+=128){
        int d=0,rem=t,len=32; while(rem>=len){rem-=len;++d;--len;}
        dtab[t]=(u16)((d<<8)|(d+rem));
    }

    const int gidx = blockIdx.x*4 + wid;
    const bool is_k = gidx >= BATCH*SQN;
    const int idx = is_k ? gidx-BATCH*SQN : gidx;
    const float* cov =(is_k?k_cov :q_cov )+(size_t)idx*1024;
    const float* mean=(is_k?k_mean:q_mean)+(size_t)idx*32;

    float m[32];
    #pragma unroll
    for(int i=0;i<8;i++){
        float4 v=*(const float4*)(cov+lane*32+i*4);
        m[i*4]=v.x; m[i*4+1]=v.y; m[i*4+2]=v.z; m[i*4+3]=v.w;
    }
    #pragma unroll
    for(int i=0;i<32;i++) cov_s[wid][lane*33+i]=m[i];
    float mean_v = mean[lane];
    __syncthreads();

    #pragma unroll
    for(int p=0;p<32;p++){
        float colp[32];
        #pragma unroll
        for(int r=0;r<32;r++) colp[r]=__shfl_sync(0xffffffffu,m[r],p);
        float dpi = 1.f/colp[p];
        bool isp = (lane==p);
        float rowp = (isp?1.f:m[p])*dpi;
        m[p]=rowp;
        #pragma unroll
        for(int r=0;r<32;r++){
            if(r==p) continue;
            float base = isp ? 0.f : m[r];
            m[r] = fmaf(-colp[r], rowp, base);
        }
    }

    float u=0.f;
    #pragma unroll
    for(int r=0;r<32;r++) u=fmaf(m[r],__shfl_sync(0xffffffffu,mean_v,r),u);
    float s = u*mean_v;
    #pragma unroll
    for(int o=16;o;o>>=1) s += __shfl_xor_sync(0xffffffffu,s,o);

    #pragma unroll
    for(int r=0;r<32;r++) inv_s[wid][r*33+lane]=m[r];
    mean_sh[wid][lane]=mean_v;
    u_sh[wid][lane]=u;
    __syncwarp();

    const float* iw = inv_s[wid];
    const float* cs = cov_s[wid];
    const float* ms = mean_sh[wid];
    const float* us = u_sh[wid];
    u32* rowp=(u32*)((is_k?g_G:g_F)+(size_t)idx*2304);

    #pragma unroll 1
    for(int i=0;i<18;i++){
        int j=i*32+lane;
        float x0,x1;
        if(j<264){
            #pragma unroll
            for(int h=0;h<2;h++){
                int t=2*j+h;
                u16 de=dtab[t]; int d=de>>8, e=de&255;
                float cv=cs[d*33+e];
                float val=cv+ms[d]*ms[e];
                float iv=iw[d*33+e];
                float dbl=(d==e)?1.f:2.f;
                float x = is_k ? iv : val*dbl;
                if(h) x1=x; else x0=x;
            }
        } else if(j<528){
            #pragma unroll
            for(int h=0;h<2;h++){
                int t=2*j-528+h;
                u16 de=dtab[t]; int d=de>>8, e=de&255;
                float cv=cs[d*33+e];
                float val=cv+ms[d]*ms[e];
                float iv=iw[d*33+e];
                float dbl=(d==e)?1.f:2.f;
                float x = is_k ? val : iv*dbl;
                if(h) x1=x; else x0=x;
            }
        } else if(j<544){
            int r=2*(j-528);
            if(!is_k){ x0=-2.f*ms[r]; x1=-2.f*ms[r+1]; }
            else     { x0=us[r];      x1=us[r+1];      }
        } else if(j<560){
            int r=2*(j-544);
            if(!is_k){ x0=-2.f*us[r]; x1=-2.f*us[r+1]; }
            else     { x0=ms[r];      x1=ms[r+1];      }
        } else if(j==560){
            if(!is_k){ x0=s; x1=1.f; } else { x0=1.f; x1=s; }
        } else { x0=0.f; x1=0.f; }
        rowp[j]    =hilo(x0,x1,0);
        rowp[576+j]=hilo(x0,x1,1);
    }
}

// ---------------------------------------------------------------- vcov transpose+split
__global__ void __launch_bounds__(256) vsplit_kernel(const float* __restrict__ vcov)
{
    __shared__ float ts[64*129];
    const int n0=blockIdx.x*128, k0=blockIdx.y*64, b=blockIdx.z, tid=threadIdx.x;
    const float* src=vcov+((size_t)b*512+k0)*1024+n0;
    for(int i=tid;i<8192;i+=256){ int kk=i>>7,nn=i&127; ts[kk*129+nn]=src[(size_t)kk*1024+nn]; }
    __syncthreads();
    u32* dst=(u32*)g_V;
    for(int i=tid;i<4096;i+=256){
        int nl=i>>5, kp=i&31;
        float x0=ts[(kp*2)*129+nl], x1=ts[(kp*2+1)*129+nl];
        size_t rb=((size_t)b*1152+n0+nl)*512;
        dst[rb+(blockIdx.y*32)+kp]     =hilo(x0,x1,0);
        dst[rb+256+(blockIdx.y*32)+kp] =hilo(x0,x1,1);
    }
}

// ---------------------------------------------------------------- vmean transpose+split
__global__ void __launch_bounds__(256) vmsplit_kernel(const float* __restrict__ vmean)
{
    const int b=blockIdx.x, tid=threadIdx.x;
    for(int i=tid;i<32*512;i+=256){
        int d=i>>9, k=i&511;
        float x=vmean[((size_t)b*512+k)*32+d];
        u16 hi=f2h(x), lo=f2h(x-h2f(hi));
        u16* row=g_V+((size_t)b*1152+1024+d)*1024;
        row[k]=hi; row[512+k]=lo;
    }
}

// ---------------------------------------------------------------- softmax: warp per row; sums split-K partials; emits fp16 hi only
__global__ void __launch_bounds__(256) softmax_kernel()
{
    const int tid=threadIdx.x, wid=tid>>5, lane=tid&31;
    const int gid=blockIdx.x*8+wid;
    const float* r1=g_js +(size_t)gid*512;
    const float* r2=g_js2+(size_t)gid*512;
    float4 v[4];
    #pragma unroll
    for(int i=0;i<4;i++){
        float4 a=*(const float4*)(r1+(lane+i*32)*4);
        float4 b=*(const float4*)(r2+(lane+i*32)*4);
        v[i]=make_float4(0.25f*(a.x+b.x),0.25f*(a.y+b.y),0.25f*(a.z+b.z),0.25f*(a.w+b.w));
    }
    float mx=-1e30f;
    #pragma unroll
    for(int i=0;i<4;i++) mx=fmaxf(mx,fmaxf(fmaxf(v[i].x,v[i].y),fmaxf(v[i].z,v[i].w)));
    #pragma unroll
    for(int o=16;o;o>>=1) mx=fmaxf(mx,__shfl_xor_sync(0xffffffffu,mx,o));
    float sum=0.f;
    #pragma unroll
    for(int i=0;i<4;i++){
        v[i].x=__expf(v[i].x-mx); v[i].y=__expf(v[i].y-mx);
        v[i].z=__expf(v[i].z-mx); v[i].w=__expf(v[i].w-mx);
        sum+=v[i].x+v[i].y+v[i].z+v[i].w;
    }
    #pragma unroll
    for(int o=16;o;o>>=1) sum+=__shfl_xor_sync(0xffffffffu,sum,o);
    float inv=1.f/sum;
    u32* srow=(u32*)(g_S+(size_t)gid*512);
    #pragma unroll
    for(int i=0;i<4;i++){
        float a0=v[i].x*inv, a1=v[i].y*inv, a2=v[i].z*inv, a3=v[i].w*inv;
        uint2 hi=make_uint2(hilo(a0,a1,0),hilo(a2,a3,0));
        *(uint2*)(srow+(lane+i*32)*2)=hi;
    }
}

// ---------------------------------------------------------------- fp16 mma.sync GEMM
// MODE 0: js split-K, 3 K-blocks [FhiGhi|FhiGlo|FloGhi] (A=g_F,B=g_G,C=g_js/g_js2).
// MODE 1: out_cov+out_mean, 2 K-blocks [ShiVhi|ShiVlo] (A=g_S,B=g_V).
// NT, 128x64 CTA tile, 8 warps (32x32), K-chunks of 32.
// 4-stage cp.async pipeline (wait_group 2) + fragment double-buffering.
#define SSTG 12288          // (128+64) rows * 64B
template<int NK,int KCH,int HL,int LDA,int LDB,int NBROWS,int LDC,int MODE,int NBM,int NSPLIT>
__global__ void __launch_bounds__(256,2) gemm_mma(float* __restrict__ Carg,
                                                  float* __restrict__ Cmean)
{
    __shared__ __align__(16) u16 smem[4*SSTG/2];   // 49152 bytes
    __shared__ int2 offs_s[NK];
    const int tid=threadIdx.x, wid=tid>>5, lane=tid&31;
    const int wm=wid&3, wn=wid>>2;                // warp tile: rows wm*32, cols wn*32
    const int nb=blockIdx.x, mb=blockIdx.y, zz=blockIdx.z;
    const int b   = (NSPLIT==2) ? (zz&(BATCH-1)) : zz;
    const int half= (NSPLIT==2) ? (zz>>3) : 0;
    const u32 sb=sptr(smem);

    const u16* Ag = (MODE==0) ? g_F : g_S;
    const u16* Bg = (MODE==0) ? g_G : g_V;
    float*     Cg = (MODE==0) ? (half ? g_js2 : g_js) : Carg;

    const u16* Ab=Ag+(size_t)(b*512   +mb*128)*LDA;
    const u16* Bb=Bg+(size_t)(b*NBROWS+nb*64 )*LDB;

    // K-chunk offset table
    for(int i=tid;i<NK;i+=256){
        int gt=i+half*NK;
        int blk=gt/KCH, tt=gt-blk*KCH;
        if(MODE==0) offs_s[i]=make_int2(((blk==2)?HL:0)+tt*32, ((blk==1)?HL:0)+tt*32);
        else        offs_s[i]=make_int2(tt*32, blk*HL+tt*32);   // A reads Shi both blocks
    }

    // per-thread transfer pointers/offsets
    const int trow=tid>>2, tseg=tid&3;
    const u16* gA0=Ab+(size_t)trow*LDA+tseg*8;
    const u16* gA1=Ab+(size_t)(trow+64)*LDA+tseg*8;
    const u16* gB =Bb+(size_t)trow*LDB+tseg*8;
    const u32 dA0=SWZ64((u32)(trow*64+tseg*16));
    const u32 dA1=SWZ64((u32)((trow+64)*64+tseg*16));
    const u32 dB =8192u+SWZ64((u32)(trow*64+tseg*16));

    auto load=[&](int t,u32 so){
        int2 o=offs_s[t];
        asm volatile("cp.async.cg.shared.global [%0],[%1],16;"::"r"(so+dA0),"l"(gA0+o.x));
        asm volatile("cp.async.cg.shared.global [%0],[%1],16;"::"r"(so+dA1),"l"(gA1+o.x));
        asm volatile("cp.async.cg.shared.global [%0],[%1],16;"::"r"(so+dB ),"l"(gB +o.y));
        asm volatile("cp.async.commit_group;":::"memory");
    };

    // lane-constant ldmatrix byte offsets within a stage
    const int lr=lane&15, lc=(lane>>4)*8;
    u32 aof[2][2], bof[2][2];
    #pragma unroll
    for(int f=0;f<2;f++)
        #pragma unroll
        for(int ks=0;ks<2;ks++)
            aof[f][ks]=SWZ64((u32)((wm*32+f*16+lr)*64 + (ks*16+lc)*2));
    #pragma unroll
    for(int g2=0;g2<2;g2++)
        #pragma unroll
        for(int ks=0;ks<2;ks++)
            bof[g2][ks]=8192u+SWZ64((u32)((wn*32+g2*16+lr)*64 + (ks*16+lc)*2));

    // fragment double buffers
    u32 fa[2][2][4], fb[2][2][4];
    auto ldfrag=[&](int buf,u32 s0,int ks){
        #pragma unroll
        for(int f=0;f<2;f++)
            asm volatile("ldmatrix.sync.aligned.m8n8.x4.shared.b16 {%0,%1,%2,%3},[%4];"
                :"=r"(fa[buf][f][0]),"=r"(fa[buf][f][1]),"=r"(fa[buf][f][2]),"=r"(fa[buf][f][3])
                :"r"(s0+aof[f][ks]));
        #pragma unroll
        for(int g2=0;g2<2;g2++)
            asm volatile("ldmatrix.sync.aligned.m8n8.x4.shared.b16 {%0,%1,%2,%3},[%4];"
                :"=r"(fb[buf][g2][0]),"=r"(fb[buf][g2][1]),"=r"(fb[buf][g2][2]),"=r"(fb[buf][g2][3])
                :"r"(s0+bof[g2][ks]));
    };

    float acc[2][4][4];
    #pragma unroll
    for(int f=0;f<2;f++)
        #pragma unroll
        for(int n=0;n<4;n++)
            #pragma unroll
            for(int e=0;e<4;e++) acc[f][n][e]=0.f;

    auto mmab=[&](int buf){
        #pragma unroll
        for(int f=0;f<2;f++)
            #pragma unroll
            for(int n=0;n<4;n++)
                asm volatile("mma.sync.aligned.m16n8k16.row.col.f32.f16.f16.f32 "
                    "{%0,%1,%2,%3},{%4,%5,%6,%7},{%8,%9},{%0,%1,%2,%3};"
                    :"+f"(acc[f][n][0]),"+f"(acc[f][n][1]),"+f"(acc[f][n][2]),"+f"(acc[f][n][3])
                    :"r"(fa[buf][f][0]),"r"(fa[buf][f][1]),"r"(fa[buf][f][2]),"r"(fa[buf][f][3]),
                     "r"(fb[buf][n>>1][n&1]),"r"(fb[buf][n>>1][(n&1)+2]));
    };

    __syncthreads();   // offs_s ready
    load(0,sb); load(1,sb+SSTG); load(2,sb+2*SSTG);
    asm volatile("cp.async.wait_group 2;":::"memory");
    __syncthreads();                       // stage 0 ready for all warps
    ldfrag(0,sb,0);                        // frags (chunk0, ks0)
    int cur=0, nxt=3;

    #pragma unroll 1
    for(int t=0;t<NK;t++){
        const u32 s0=sb+cur*SSTG;
        ldfrag(1,s0,1);                    // frags (t,ks1) — overlaps mma below
        mmab(0);                           // mma (t,ks0)
        if(t+3<NK){ load(t+3, sb+nxt*SSTG); nxt=(nxt+1)&3; }
        if(t+1<NK){
            if(NK-1-t>=3)      asm volatile("cp.async.wait_group 2;":::"memory");
            else if(NK-1-t==2) asm volatile("cp.async.wait_group 1;":::"memory");
            else               asm volatile("cp.async.wait_group 0;":::"memory");
            __syncthreads();               // stage t+1 visible to all warps
            cur=(cur+1)&3;
            ldfrag(0, sb+cur*SSTG, 0);     // frags (t+1,ks0) — overlaps mma below
        }
        mmab(1);                           // mma (t,ks1)
    }

    const int fr=lane>>2, fc=lane&3;
    if(MODE==1 && nb==NBM){
        if(wn!=0) return;   // only cols 0..31 valid (vmean^T rows 1024..1055)
        float* Cb=Cmean+((size_t)(b*512+mb*128+wm*32))*32;
        #pragma unroll
        for(int f=0;f<2;f++)
            #pragma unroll
            for(int n=0;n<4;n++){
                *(float2*)(Cb+(size_t)(f*16+fr  )*32+n*8+fc*2)=make_float2(acc[f][n][0],acc[f][n][1]);
                *(float2*)(Cb+(size_t)(f*16+fr+8)*32+n*8+fc*2)=make_float2(acc[f][n][2],acc[f][n][3]);
            }
        return;
    }

    float* Cb=Cg+((size_t)(b*512+mb*128+wm*32))*LDC + nb*64 + wn*32;
    #pragma unroll
    for(int f=0;f<2;f++)
        #pragma unroll
        for(int n=0;n<4;n++){
            *(float2*)(Cb+(size_t)(f*16+fr  )*LDC+n*8+fc*2)=make_float2(acc[f][n][0],acc[f][n][1]);
            *(float2*)(Cb+(size_t)(f*16+fr+8)*LDC+n*8+fc*2)=make_float2(acc[f][n][2],acc[f][n][3]);
        }
}

// ---------------------------------------------------------------- launch
extern "C" void kernel_launch(void* const* d_in, const int* in_sizes, int n_in,
                              void* d_out, int out_size)
{
    const float* q_mean=(const float*)d_in[0];
    const float* q_cov =(const float*)d_in[1];
    const float* k_mean=(const float*)d_in[2];
    const float* k_cov =(const float*)d_in[3];
    const float* v_mean=(const float*)d_in[4];
    const float* v_cov =(const float*)d_in[5];
    float* out=(float*)d_out;

    // side stream + events, created once on the first (uncaptured) call
    static cudaStream_t s2 = [](){ cudaStream_t s; cudaStreamCreate(&s); return s; }();
    static cudaEvent_t evFork = [](){ cudaEvent_t e; cudaEventCreateWithFlags(&e,cudaEventDisableTiming); return e; }();
    static cudaEvent_t evJoin = [](){ cudaEvent_t e; cudaEventCreateWithFlags(&e,cudaEventDisableTiming); return e; }();
    static bool attrs_set = [](){
        cudaFuncSetAttribute(gemm_mma<54,36,1152,2304,2304,512,512,0,-1,2>,
                             cudaFuncAttributePreferredSharedMemoryCarveout, 100);
        cudaFuncSetAttribute(gemm_mma<32,16,512,512,1024,1152,1024,1,16,1>,
                             cudaFuncAttributePreferredSharedMemoryCarveout, 100);
        return true;
    }();
    (void)attrs_set;

    // fork: v-side prep runs concurrently with feat/js/softmax
    cudaEventRecord(evFork, 0);
    cudaStreamWaitEvent(s2, evFork, 0);
    vsplit_kernel<<<dim3(8,8,BATCH),256,0,s2>>>(v_cov);
    vmsplit_kernel<<<BATCH,256,0,s2>>>(v_mean);
    cudaEventRecord(evJoin, s2);

    // main chain
    feat_kernel<<<2*BATCH*SQN/4,128>>>(q_mean,q_cov,k_mean,k_cov);
    // js split-K=2: 54 chunks per half; grid 8x4x16 = 512 CTAs
    gemm_mma<54,36,1152,2304,2304,512,512,0,-1,2>
        <<<dim3(8,4,BATCH*2),256>>>(nullptr,nullptr);
    softmax_kernel<<<BATCH*SQN/8,256>>>();

    // join: ocov needs g_V
    cudaStreamWaitEvent(0, evJoin, 0);
    // out_cov (+fused out_mean as 17th N-tile): 2 K-blocks -> 32 chunks; grid 544
    gemm_mma<32,16,512,512,1024,1152,1024,1,16,1>
        <<<dim3(17,4,BATCH),256>>>(out+(size_t)BATCH*SQN*DDIM, out);
}